// round 2
// baseline (speedup 1.0000x reference)
#include <cuda_runtime.h>
#include <math.h>

#define N_NODES 81
#define N_EDGES 1620
#define IN_DIM 10
#define HIDDEN 8192
#define ACTIONS 729

// Scratch (no allocations allowed -> __device__ globals)
__device__ float d_h[N_NODES * HIDDEN];    // x @ W_gcn
__device__ float d_h2[N_NODES * HIDDEN];   // relu(aggregate + b)
__device__ float d_g[HIDDEN];              // pooled graph vector
__device__ float d_t1[HIDDEN];             // g @ W1 accumulator (split-K atomics)
__device__ float d_logits[ACTIONS];        // @ W2 accumulator
__device__ float d_dinv[N_NODES];
__device__ float d_mu[N_NODES];
__device__ float d_rstd[N_NODES];

// K0: degrees -> dinv, zero accumulators   (edge_index arrives as int32)
__global__ void k0_prep(const int* __restrict__ edge) {
    __shared__ int cnt[N_NODES];
    int tid = threadIdx.x;
    for (int i = tid; i < N_NODES; i += blockDim.x) cnt[i] = 0;
    __syncthreads();
    for (int e = tid; e < N_EDGES; e += blockDim.x) {
        int d = edge[N_EDGES + e];                    // dst counts
        if (d >= 0 && d < N_NODES) atomicAdd(&cnt[d], 1);
    }
    __syncthreads();
    for (int i = tid; i < N_NODES; i += blockDim.x)
        d_dinv[i] = rsqrtf((float)(cnt[i] + 1));      // +1 self loop
    for (int i = tid; i < HIDDEN; i += blockDim.x) d_t1[i] = 0.f;
    for (int i = tid; i < ACTIONS; i += blockDim.x) d_logits[i] = 0.f;
}

// K1: h = x @ W_gcn   [81,10] @ [10,8192]
__global__ void k1_transform(const float* __restrict__ x, const float* __restrict__ Wg) {
    int i = blockIdx.x * blockDim.x + threadIdx.x;   // [0, 81*8192)
    int n = i >> 13;
    int j = i & (HIDDEN - 1);
    float acc = 0.f;
#pragma unroll
    for (int k = 0; k < IN_DIM; k++)
        acc += x[n * IN_DIM + k] * Wg[k * HIDDEN + j];
    d_h[i] = acc;
}

// K2: symmetric-normalized aggregation + bias + relu.
// Each thread owns one hidden column; per-node partials live in shared memory.
__global__ void k2_agg(const int* __restrict__ edge, const float* __restrict__ bg) {
    __shared__ float acc[N_NODES * 128];
    __shared__ float sdinv[N_NODES];
    int tid = threadIdx.x;
    int j = blockIdx.x * 128 + tid;
    if (tid < N_NODES) sdinv[tid] = d_dinv[tid];
    for (int n = 0; n < N_NODES; n++) acc[n * 128 + tid] = 0.f;
    __syncthreads();
    // self loops
    for (int n = 0; n < N_NODES; n++) {
        float dv = sdinv[n];
        acc[n * 128 + tid] += d_h[n * HIDDEN + j] * dv * dv;
    }
    // edges (edge reads are warp-uniform -> broadcast, L1/L2 cached)
#pragma unroll 4
    for (int e = 0; e < N_EDGES; e++) {
        int s = edge[e];
        int d = edge[N_EDGES + e];
        if (((unsigned)s < N_NODES) && ((unsigned)d < N_NODES))
            acc[d * 128 + tid] += d_h[s * HIDDEN + j] * (sdinv[s] * sdinv[d]);
    }
    float b = bg[j];
    for (int n = 0; n < N_NODES; n++) {
        float v = acc[n * 128 + tid] + b;
        d_h2[n * HIDDEN + j] = v > 0.f ? v : 0.f;
    }
}

// K3: per-node LayerNorm stats
__global__ void k3_stats() {
    int n = blockIdx.x;
    int tid = threadIdx.x;
    float s = 0.f, sq = 0.f;
    for (int j = tid; j < HIDDEN; j += blockDim.x) {
        float v = d_h2[n * HIDDEN + j];
        s += v;
        sq += v * v;
    }
    __shared__ float ss[256], ssq[256];
    ss[tid] = s; ssq[tid] = sq;
    __syncthreads();
    for (int o = 128; o > 0; o >>= 1) {
        if (tid < o) { ss[tid] += ss[tid + o]; ssq[tid] += ssq[tid + o]; }
        __syncthreads();
    }
    if (tid == 0) {
        float mu = ss[0] / HIDDEN;
        float var = ssq[0] / HIDDEN - mu * mu;
        d_mu[n] = mu;
        d_rstd[n] = rsqrtf(var + 1e-5f);
    }
}

// K4: fused layernorm + global_add_pool:
// g[j] = ln_g[j] * sum_n (h2[n,j]-mu[n])*rstd[n]  +  81*ln_b[j]
__global__ void k4_pool(const float* __restrict__ lg, const float* __restrict__ lb) {
    int j = blockIdx.x * blockDim.x + threadIdx.x;
    float acc = 0.f;
#pragma unroll 3
    for (int n = 0; n < N_NODES; n++)
        acc += (d_h2[n * HIDDEN + j] - d_mu[n]) * d_rstd[n];
    d_g[j] = lg[j] * acc + (float)N_NODES * lb[j];
}

// K6: split-K GEMV: t1 += g @ W1. float4 loads, 512 blocks to saturate HBM.
__global__ void k6_gemv1(const float* __restrict__ W1) {
    int col = blockIdx.x * 1024 + threadIdx.x * 4;
    int k0 = blockIdx.y * 128;
    const float4* Wv = reinterpret_cast<const float4*>(W1);
    int ci = col >> 2;
    float4 acc = make_float4(0.f, 0.f, 0.f, 0.f);
#pragma unroll 4
    for (int k = k0; k < k0 + 128; k++) {
        float gk = d_g[k];
        float4 w = Wv[(size_t)k * (HIDDEN / 4) + ci];
        acc.x += gk * w.x; acc.y += gk * w.y;
        acc.z += gk * w.z; acc.w += gk * w.w;
    }
    atomicAdd(&d_t1[col + 0], acc.x);
    atomicAdd(&d_t1[col + 1], acc.y);
    atomicAdd(&d_t1[col + 2], acc.z);
    atomicAdd(&d_t1[col + 3], acc.w);
}

// K7: logits += relu(t1 + b1) @ W2  (split-K)
__global__ void k7_gemv2(const float* __restrict__ W2, const float* __restrict__ b1) {
    int j = blockIdx.x * 256 + threadIdx.x;
    int k0 = blockIdx.y * 64;
    if (j >= ACTIONS) return;
    float acc = 0.f;
#pragma unroll 4
    for (int k = k0; k < k0 + 64; k++) {
        float a = d_t1[k] + b1[k];
        a = a > 0.f ? a : 0.f;
        acc += a * W2[(size_t)k * ACTIONS + j];
    }
    atomicAdd(&d_logits[j], acc);
}

// K8: log_softmax over 729 logits (+ b2)
__global__ void k8_softmax(const float* __restrict__ b2, float* __restrict__ out) {
    __shared__ float sh[1024];
    int tid = threadIdx.x;
    float l = (tid < ACTIONS) ? d_logits[tid] + b2[tid] : -INFINITY;
    sh[tid] = l;
    __syncthreads();
    for (int o = 512; o > 0; o >>= 1) {
        if (tid < o) sh[tid] = fmaxf(sh[tid], sh[tid + o]);
        __syncthreads();
    }
    float mx = sh[0];
    __syncthreads();
    float ex = (tid < ACTIONS) ? expf(l - mx) : 0.f;
    sh[tid] = ex;
    __syncthreads();
    for (int o = 512; o > 0; o >>= 1) {
        if (tid < o) sh[tid] += sh[tid + o];
        __syncthreads();
    }
    float lse = logf(sh[0]);
    if (tid < ACTIONS) out[tid] = l - mx - lse;
}

extern "C" void kernel_launch(void* const* d_in, const int* in_sizes, int n_in,
                              void* d_out, int out_size) {
    const float* x    = (const float*)d_in[0];
    const int*   edge = (const int*)d_in[1];          // int64 in reference -> int32 from harness
    const float* Wg   = (const float*)d_in[2];
    const float* bg   = (const float*)d_in[3];
    const float* lng  = (const float*)d_in[4];
    const float* lnb  = (const float*)d_in[5];
    const float* W1   = (const float*)d_in[6];
    const float* b1   = (const float*)d_in[7];
    const float* W2   = (const float*)d_in[8];
    const float* b2   = (const float*)d_in[9];
    float* out = (float*)d_out;

    k0_prep<<<1, 256>>>(edge);
    k1_transform<<<(N_NODES * HIDDEN) / 256, 256>>>(x, Wg);
    k2_agg<<<HIDDEN / 128, 128>>>(edge, bg);
    k3_stats<<<N_NODES, 256>>>();
    k4_pool<<<HIDDEN / 256, 256>>>(lng, lnb);
    k6_gemv1<<<dim3(8, 64), 256>>>(W1);
    k7_gemv2<<<dim3(3, 128), 256>>>(W2, b1);
    k8_softmax<<<1, 1024>>>(b2, out);
}

// round 3
// speedup vs baseline: 2.5703x; 2.5703x over previous
#include <cuda_runtime.h>
#include <math.h>

#define N_NODES 81
#define N_EDGES 1620
#define IN_DIM 10
#define HIDDEN 8192
#define ACTIONS 729

// Scratch (__device__ globals; no allocation allowed)
__device__ float d_h[N_NODES * HIDDEN];     // x @ W_gcn
__device__ float d_h2[N_NODES * HIDDEN];    // relu(aggregate + b)
__device__ float d_g[HIDDEN];               // pooled graph vector
__device__ float d_t1[HIDDEN];              // g @ W1 accumulator
__device__ float d_logits[ACTIONS];
__device__ float d_dinv[N_NODES];
__device__ float d_nsum[N_NODES];           // per-node sum(relu h)
__device__ float d_nsq[N_NODES];            // per-node sum(relu h ^2)
__device__ int   d_csr_src[N_EDGES];        // incoming-edge src, grouped by dst
__device__ float d_csr_w[N_EDGES];          // dinv[s]*dinv[d] per sorted edge
__device__ int   d_off[N_NODES + 1];

// ---------------------------------------------------------------------------
// K0: build dst-grouped CSR + norm weights, zero accumulators. 1 block.
__global__ void k0_prep(const int* __restrict__ edge) {
    __shared__ int cnt[N_NODES];
    __shared__ int off[N_NODES + 1];
    __shared__ float sdinv[N_NODES];
    int tid = threadIdx.x;
    for (int i = tid; i < N_NODES; i += blockDim.x) cnt[i] = 0;
    __syncthreads();
    for (int e = tid; e < N_EDGES; e += blockDim.x) {
        int d = edge[N_EDGES + e];
        if ((unsigned)d < N_NODES) atomicAdd(&cnt[d], 1);
    }
    __syncthreads();
    for (int i = tid; i < N_NODES; i += blockDim.x) {
        float dv = rsqrtf((float)(cnt[i] + 1));   // +1 self loop
        sdinv[i] = dv;
        d_dinv[i] = dv;
    }
    __syncthreads();
    if (tid == 0) {
        off[0] = 0;
        for (int i = 0; i < N_NODES; i++) off[i + 1] = off[i] + cnt[i];
    }
    __syncthreads();
    for (int i = tid; i <= N_NODES; i += blockDim.x) d_off[i] = off[i];
    // reuse cnt as scatter cursor
    for (int i = tid; i < N_NODES; i += blockDim.x) cnt[i] = off[i];
    __syncthreads();
    for (int e = tid; e < N_EDGES; e += blockDim.x) {
        int s = edge[e];
        int d = edge[N_EDGES + e];
        if ((unsigned)s < N_NODES && (unsigned)d < N_NODES) {
            int pos = atomicAdd(&cnt[d], 1);
            d_csr_src[pos] = s;
            d_csr_w[pos] = sdinv[s] * sdinv[d];
        }
    }
    // zero accumulators
    for (int i = tid; i < HIDDEN; i += blockDim.x) d_t1[i] = 0.f;
    for (int i = tid; i < ACTIONS; i += blockDim.x) d_logits[i] = 0.f;
    for (int i = tid; i < N_NODES; i += blockDim.x) { d_nsum[i] = 0.f; d_nsq[i] = 0.f; }
}

// ---------------------------------------------------------------------------
// K1: h = x @ W_gcn   [81,10] @ [10,8192]
__global__ void k1_transform(const float* __restrict__ x, const float* __restrict__ Wg) {
    int i = blockIdx.x * blockDim.x + threadIdx.x;
    int n = i >> 13;
    int j = i & (HIDDEN - 1);
    float acc = 0.f;
#pragma unroll
    for (int k = 0; k < IN_DIM; k++)
        acc += x[n * IN_DIM + k] * Wg[k * HIDDEN + j];
    d_h[i] = acc;
}

// ---------------------------------------------------------------------------
// K2: per-dst aggregation via CSR + bias + relu + LN partial sums.
// grid (32 col-chunks, 81 nodes), 256 threads.
__global__ void k2_agg(const float* __restrict__ bg) {
    __shared__ int   s_src[256];
    __shared__ float s_w[256];
    __shared__ float red[256];
    int tid = threadIdx.x;
    int n = blockIdx.y;
    int j = blockIdx.x * 256 + tid;

    float dv = d_dinv[n];
    float acc = d_h[n * HIDDEN + j] * dv * dv;     // self loop
    int beg = d_off[n], end = d_off[n + 1];
    for (int base = beg; base < end; base += 256) {
        int m = min(256, end - base);
        if (tid < m) { s_src[tid] = d_csr_src[base + tid]; s_w[tid] = d_csr_w[base + tid]; }
        __syncthreads();
        for (int i = 0; i < m; i++)
            acc += d_h[s_src[i] * HIDDEN + j] * s_w[i];
        __syncthreads();
    }
    float v = acc + bg[j];
    v = v > 0.f ? v : 0.f;
    d_h2[n * HIDDEN + j] = v;

    // LN partial sums for this node
    red[tid] = v;
    __syncthreads();
    for (int o = 128; o > 0; o >>= 1) {
        if (tid < o) red[tid] += red[tid + o];
        __syncthreads();
    }
    if (tid == 0) atomicAdd(&d_nsum[n], red[0]);
    __syncthreads();
    red[tid] = v * v;
    __syncthreads();
    for (int o = 128; o > 0; o >>= 1) {
        if (tid < o) red[tid] += red[tid + o];
        __syncthreads();
    }
    if (tid == 0) atomicAdd(&d_nsq[n], red[0]);
}

// ---------------------------------------------------------------------------
// K4: fused layernorm + global_add_pool.
__global__ void k4_pool(const float* __restrict__ lg, const float* __restrict__ lb) {
    __shared__ float s_mu[N_NODES], s_rstd[N_NODES];
    int tid = threadIdx.x;
    if (tid < N_NODES) {
        float mu = d_nsum[tid] * (1.f / HIDDEN);
        float var = d_nsq[tid] * (1.f / HIDDEN) - mu * mu;
        s_mu[tid] = mu;
        s_rstd[tid] = rsqrtf(var + 1e-5f);
    }
    __syncthreads();
    int j = blockIdx.x * blockDim.x + tid;
    float acc = 0.f;
#pragma unroll 3
    for (int n = 0; n < N_NODES; n++)
        acc += (d_h2[n * HIDDEN + j] - s_mu[n]) * s_rstd[n];
    d_g[j] = lg[j] * acc + (float)N_NODES * lb[j];
}

// ---------------------------------------------------------------------------
// K6: split-K GEMV t1 += g @ W1. 1024 blocks, float4, unroll 8.
__global__ void k6_gemv1(const float* __restrict__ W1) {
    int col = blockIdx.x * 1024 + threadIdx.x * 4;
    int k0 = blockIdx.y * 64;
    const float4* Wv = reinterpret_cast<const float4*>(W1);
    int ci = col >> 2;
    float4 acc = make_float4(0.f, 0.f, 0.f, 0.f);
#pragma unroll 8
    for (int k = k0; k < k0 + 64; k++) {
        float gk = __ldg(&d_g[k]);
        float4 w = Wv[(size_t)k * (HIDDEN / 4) + ci];
        acc.x += gk * w.x; acc.y += gk * w.y;
        acc.z += gk * w.z; acc.w += gk * w.w;
    }
    atomicAdd(&d_t1[col + 0], acc.x);
    atomicAdd(&d_t1[col + 1], acc.y);
    atomicAdd(&d_t1[col + 2], acc.z);
    atomicAdd(&d_t1[col + 3], acc.w);
}

// ---------------------------------------------------------------------------
// K7: logits += relu(t1 + b1) @ W2 (split-K)
__global__ void k7_gemv2(const float* __restrict__ W2, const float* __restrict__ b1) {
    int j = blockIdx.x * 256 + threadIdx.x;
    int k0 = blockIdx.y * 64;
    if (j >= ACTIONS) return;
    float acc = 0.f;
#pragma unroll 4
    for (int k = k0; k < k0 + 64; k++) {
        float a = d_t1[k] + b1[k];
        a = a > 0.f ? a : 0.f;
        acc += a * W2[(size_t)k * ACTIONS + j];
    }
    atomicAdd(&d_logits[j], acc);
}

// ---------------------------------------------------------------------------
// K8: log_softmax
__global__ void k8_softmax(const float* __restrict__ b2, float* __restrict__ out) {
    __shared__ float sh[1024];
    int tid = threadIdx.x;
    float l = (tid < ACTIONS) ? d_logits[tid] + b2[tid] : -INFINITY;
    sh[tid] = l;
    __syncthreads();
    for (int o = 512; o > 0; o >>= 1) {
        if (tid < o) sh[tid] = fmaxf(sh[tid], sh[tid + o]);
        __syncthreads();
    }
    float mx = sh[0];
    __syncthreads();
    float ex = (tid < ACTIONS) ? expf(l - mx) : 0.f;
    sh[tid] = ex;
    __syncthreads();
    for (int o = 512; o > 0; o >>= 1) {
        if (tid < o) sh[tid] += sh[tid + o];
        __syncthreads();
    }
    float lse = logf(sh[0]);
    if (tid < ACTIONS) out[tid] = l - mx - lse;
}

extern "C" void kernel_launch(void* const* d_in, const int* in_sizes, int n_in,
                              void* d_out, int out_size) {
    const float* x    = (const float*)d_in[0];
    const int*   edge = (const int*)d_in[1];
    const float* Wg   = (const float*)d_in[2];
    const float* bg   = (const float*)d_in[3];
    const float* lng  = (const float*)d_in[4];
    const float* lnb  = (const float*)d_in[5];
    const float* W1   = (const float*)d_in[6];
    const float* b1   = (const float*)d_in[7];
    const float* W2   = (const float*)d_in[8];
    const float* b2   = (const float*)d_in[9];
    float* out = (float*)d_out;

    k0_prep<<<1, 256>>>(edge);
    k1_transform<<<(N_NODES * HIDDEN) / 256, 256>>>(x, Wg);
    k2_agg<<<dim3(HIDDEN / 256, N_NODES), 256>>>(bg);
    k4_pool<<<HIDDEN / 256, 256>>>(lng, lnb);
    k6_gemv1<<<dim3(8, 128), 256>>>(W1);
    k7_gemv2<<<dim3(3, 128), 256>>>(W2, b1);
    k8_softmax<<<1, 1024>>>(b2, out);
}

// round 4
// speedup vs baseline: 2.7249x; 1.0602x over previous
#include <cuda_runtime.h>
#include <math.h>

#define N_NODES 81
#define N_EDGES 1620
#define IN_DIM 10
#define HIDDEN 8192
#define ACTIONS 729

// Scratch (__device__ globals; no allocation allowed)
__device__ float d_h2[N_NODES * HIDDEN];    // relu(aggregate + b)
__device__ float d_gacc[HIDDEN];            // pooled LN accumulator (pre gamma/beta)
__device__ float d_t1[HIDDEN];              // g @ W1 accumulator
__device__ float d_logits[ACTIONS];
__device__ float d_dinv[N_NODES];
__device__ float d_nsum[N_NODES];           // per-node sum(relu h)
__device__ float d_nsq[N_NODES];            // per-node sum(relu h ^2)
__device__ int   d_csr_src[N_EDGES];        // incoming-edge src, grouped by dst
__device__ float d_csr_w[N_EDGES];          // dinv[s]*dinv[d] per sorted edge
__device__ int   d_off[N_NODES + 1];

// ---------------------------------------------------------------------------
// K0: build dst-grouped CSR + norm weights, zero accumulators. 1 block.
__global__ void k0_prep(const int* __restrict__ edge) {
    __shared__ int cnt[N_NODES];
    __shared__ int off[N_NODES + 1];
    __shared__ float sdinv[N_NODES];
    int tid = threadIdx.x;
    for (int i = tid; i < N_NODES; i += blockDim.x) cnt[i] = 0;
    __syncthreads();
    for (int e = tid; e < N_EDGES; e += blockDim.x) {
        int d = edge[N_EDGES + e];
        if ((unsigned)d < N_NODES) atomicAdd(&cnt[d], 1);
    }
    __syncthreads();
    for (int i = tid; i < N_NODES; i += blockDim.x) {
        float dv = rsqrtf((float)(cnt[i] + 1));   // +1 self loop
        sdinv[i] = dv;
        d_dinv[i] = dv;
    }
    __syncthreads();
    if (tid == 0) {
        off[0] = 0;
        for (int i = 0; i < N_NODES; i++) off[i + 1] = off[i] + cnt[i];
    }
    __syncthreads();
    for (int i = tid; i <= N_NODES; i += blockDim.x) d_off[i] = off[i];
    for (int i = tid; i < N_NODES; i += blockDim.x) cnt[i] = off[i];  // scatter cursor
    __syncthreads();
    for (int e = tid; e < N_EDGES; e += blockDim.x) {
        int s = edge[e];
        int d = edge[N_EDGES + e];
        if ((unsigned)s < N_NODES && (unsigned)d < N_NODES) {
            int pos = atomicAdd(&cnt[d], 1);
            d_csr_src[pos] = s;
            d_csr_w[pos] = sdinv[s] * sdinv[d];
        }
    }
    for (int i = tid; i < HIDDEN; i += blockDim.x) { d_t1[i] = 0.f; d_gacc[i] = 0.f; }
    for (int i = tid; i < ACTIONS; i += blockDim.x) d_logits[i] = 0.f;
    for (int i = tid; i < N_NODES; i += blockDim.x) { d_nsum[i] = 0.f; d_nsq[i] = 0.f; }
}

// ---------------------------------------------------------------------------
// K2: fused transform + aggregation + bias + relu + LN partial sums.
// grid (32 col-chunks, 81 nodes), 256 threads. h[s,j] recomputed on the fly
// from smem-resident x and register-resident Wg column (10 FMAs each).
__global__ void k2_agg(const float* __restrict__ x, const float* __restrict__ Wg,
                       const float* __restrict__ bg) {
    __shared__ float sx[N_NODES * IN_DIM];          // 810 floats
    __shared__ int   s_src[256];
    __shared__ float s_w[256];
    __shared__ float red1[256], red2[256];
    int tid = threadIdx.x;
    int n = blockIdx.y;
    int j = blockIdx.x * 256 + tid;

    for (int i = tid; i < N_NODES * IN_DIM; i += 256) sx[i] = x[i];
    float wreg[IN_DIM];
#pragma unroll
    for (int k = 0; k < IN_DIM; k++) wreg[k] = Wg[k * HIDDEN + j];
    __syncthreads();

    float dv = d_dinv[n];
    float hs = 0.f;
#pragma unroll
    for (int k = 0; k < IN_DIM; k++) hs += sx[n * IN_DIM + k] * wreg[k];
    float acc = hs * dv * dv;                        // self loop

    int beg = d_off[n], end = d_off[n + 1];
    for (int base = beg; base < end; base += 256) {
        int m = min(256, end - base);
        if (tid < m) { s_src[tid] = d_csr_src[base + tid]; s_w[tid] = d_csr_w[base + tid]; }
        __syncthreads();
        for (int i = 0; i < m; i++) {
            int s = s_src[i];
            float hv = 0.f;
#pragma unroll
            for (int k = 0; k < IN_DIM; k++) hv += sx[s * IN_DIM + k] * wreg[k];
            acc += hv * s_w[i];
        }
        __syncthreads();
    }
    float v = acc + bg[j];
    v = v > 0.f ? v : 0.f;
    d_h2[n * HIDDEN + j] = v;

    // LN partial sums (both in one reduction pass)
    red1[tid] = v;
    red2[tid] = v * v;
    __syncthreads();
    for (int o = 128; o > 0; o >>= 1) {
        if (tid < o) { red1[tid] += red1[tid + o]; red2[tid] += red2[tid + o]; }
        __syncthreads();
    }
    if (tid == 0) {
        atomicAdd(&d_nsum[n], red1[0]);
        atomicAdd(&d_nsq[n], red2[0]);
    }
}

// ---------------------------------------------------------------------------
// K4: fused layernorm + global_add_pool, node-split. grid (32, 27).
// d_gacc[j] += sum_{n in 3-node slice} (h2[n,j]-mu[n])*rstd[n]
__global__ void k4_pool() {
    __shared__ float s_mu[3], s_rstd[3];
    int tid = threadIdx.x;
    int n0 = blockIdx.y * 3;
    if (tid < 3) {
        float mu = d_nsum[n0 + tid] * (1.f / HIDDEN);
        float var = d_nsq[n0 + tid] * (1.f / HIDDEN) - mu * mu;
        s_mu[tid] = mu;
        s_rstd[tid] = rsqrtf(var + 1e-5f);
    }
    __syncthreads();
    int j = blockIdx.x * 256 + tid;
    float acc = 0.f;
#pragma unroll
    for (int t = 0; t < 3; t++)
        acc += (d_h2[(n0 + t) * HIDDEN + j] - s_mu[t]) * s_rstd[t];
    atomicAdd(&d_gacc[j], acc);
}

// ---------------------------------------------------------------------------
// K6: split-K GEMV t1 += g @ W1 with on-the-fly g finalization.
// g[k] = lg[k]*gacc[k] + N*lb[k]
__global__ void k6_gemv1(const float* __restrict__ W1, const float* __restrict__ lg,
                         const float* __restrict__ lb) {
    int col = blockIdx.x * 1024 + threadIdx.x * 4;
    int k0 = blockIdx.y * 64;
    const float4* Wv = reinterpret_cast<const float4*>(W1);
    int ci = col >> 2;
    float4 acc = make_float4(0.f, 0.f, 0.f, 0.f);
#pragma unroll 8
    for (int k = k0; k < k0 + 64; k++) {
        float gk = __ldg(&lg[k]) * d_gacc[k] + (float)N_NODES * __ldg(&lb[k]);
        float4 w = Wv[(size_t)k * (HIDDEN / 4) + ci];
        acc.x += gk * w.x; acc.y += gk * w.y;
        acc.z += gk * w.z; acc.w += gk * w.w;
    }
    atomicAdd(&d_t1[col + 0], acc.x);
    atomicAdd(&d_t1[col + 1], acc.y);
    atomicAdd(&d_t1[col + 2], acc.z);
    atomicAdd(&d_t1[col + 3], acc.w);
}

// ---------------------------------------------------------------------------
// K7: logits += relu(t1 + b1) @ W2 (split-K)
__global__ void k7_gemv2(const float* __restrict__ W2, const float* __restrict__ b1) {
    int j = blockIdx.x * 256 + threadIdx.x;
    int k0 = blockIdx.y * 64;
    if (j >= ACTIONS) return;
    float acc = 0.f;
#pragma unroll 4
    for (int k = k0; k < k0 + 64; k++) {
        float a = d_t1[k] + b1[k];
        a = a > 0.f ? a : 0.f;
        acc += a * W2[(size_t)k * ACTIONS + j];
    }
    atomicAdd(&d_logits[j], acc);
}

// ---------------------------------------------------------------------------
// K8: log_softmax
__global__ void k8_softmax(const float* __restrict__ b2, float* __restrict__ out) {
    __shared__ float sh[1024];
    int tid = threadIdx.x;
    float l = (tid < ACTIONS) ? d_logits[tid] + b2[tid] : -INFINITY;
    sh[tid] = l;
    __syncthreads();
    for (int o = 512; o > 0; o >>= 1) {
        if (tid < o) sh[tid] = fmaxf(sh[tid], sh[tid + o]);
        __syncthreads();
    }
    float mx = sh[0];
    __syncthreads();
    float ex = (tid < ACTIONS) ? expf(l - mx) : 0.f;
    sh[tid] = ex;
    __syncthreads();
    for (int o = 512; o > 0; o >>= 1) {
        if (tid < o) sh[tid] += sh[tid + o];
        __syncthreads();
    }
    float lse = logf(sh[0]);
    if (tid < ACTIONS) out[tid] = l - mx - lse;
}

extern "C" void kernel_launch(void* const* d_in, const int* in_sizes, int n_in,
                              void* d_out, int out_size) {
    const float* x    = (const float*)d_in[0];
    const int*   edge = (const int*)d_in[1];
    const float* Wg   = (const float*)d_in[2];
    const float* bg   = (const float*)d_in[3];
    const float* lng  = (const float*)d_in[4];
    const float* lnb  = (const float*)d_in[5];
    const float* W1   = (const float*)d_in[6];
    const float* b1   = (const float*)d_in[7];
    const float* W2   = (const float*)d_in[8];
    const float* b2   = (const float*)d_in[9];
    float* out = (float*)d_out;

    k0_prep<<<1, 256>>>(edge);
    k2_agg<<<dim3(HIDDEN / 256, N_NODES), 256>>>(x, Wg, bg);
    k4_pool<<<dim3(HIDDEN / 256, 27), 256>>>();
    k6_gemv1<<<dim3(8, 128), 256>>>(W1, lng, lnb);
    k7_gemv2<<<dim3(3, 128), 256>>>(W2, b1);
    k8_softmax<<<1, 1024>>>(b2, out);
}

// round 5
// speedup vs baseline: 2.8623x; 1.0504x over previous
#include <cuda_runtime.h>
#include <math.h>

#define N_NODES 81
#define N_EDGES 1620
#define IN_DIM 10
#define HIDDEN 8192
#define ACTIONS 729

// Scratch (__device__ globals; no allocation allowed)
__device__ float d_h2[N_NODES * HIDDEN];    // relu(aggregate + b)
__device__ float d_gacc[HIDDEN];            // pooled LN accumulator (pre gamma/beta)
__device__ float d_t1[HIDDEN];              // g @ W1 accumulator
__device__ float d_logits[ACTIONS];
__device__ float d_dinv[N_NODES];
__device__ float d_nsum[N_NODES];
__device__ float d_nsq[N_NODES];
__device__ int   d_csr_src[N_EDGES];
__device__ float d_csr_w[N_EDGES];
__device__ int   d_off[N_NODES + 1];

// ---------------------------------------------------------------------------
// K0: build dst-grouped CSR + norm weights, zero accumulators. 1 block.
__global__ void k0_prep(const int* __restrict__ edge) {
    __shared__ int cnt[N_NODES];
    __shared__ int off[N_NODES + 1];
    __shared__ float sdinv[N_NODES];
    int tid = threadIdx.x;
    for (int i = tid; i < N_NODES; i += blockDim.x) cnt[i] = 0;
    __syncthreads();
    for (int e = tid; e < N_EDGES; e += blockDim.x) {
        int d = edge[N_EDGES + e];
        if ((unsigned)d < N_NODES) atomicAdd(&cnt[d], 1);
    }
    __syncthreads();
    for (int i = tid; i < N_NODES; i += blockDim.x) {
        float dv = rsqrtf((float)(cnt[i] + 1));   // +1 self loop
        sdinv[i] = dv;
        d_dinv[i] = dv;
    }
    __syncthreads();
    if (tid == 0) {
        off[0] = 0;
        for (int i = 0; i < N_NODES; i++) off[i + 1] = off[i] + cnt[i];
    }
    __syncthreads();
    for (int i = tid; i <= N_NODES; i += blockDim.x) d_off[i] = off[i];
    for (int i = tid; i < N_NODES; i += blockDim.x) cnt[i] = off[i];  // scatter cursor
    __syncthreads();
    for (int e = tid; e < N_EDGES; e += blockDim.x) {
        int s = edge[e];
        int d = edge[N_EDGES + e];
        if ((unsigned)s < N_NODES && (unsigned)d < N_NODES) {
            int pos = atomicAdd(&cnt[d], 1);
            d_csr_src[pos] = s;
            d_csr_w[pos] = sdinv[s] * sdinv[d];
        }
    }
    for (int i = tid; i < HIDDEN; i += blockDim.x) { d_t1[i] = 0.f; d_gacc[i] = 0.f; }
    for (int i = tid; i < ACTIONS; i += blockDim.x) d_logits[i] = 0.f;
    for (int i = tid; i < N_NODES; i += blockDim.x) { d_nsum[i] = 0.f; d_nsq[i] = 0.f; }
}

// ---------------------------------------------------------------------------
// K2: fused transform + aggregation + bias + relu + LN partial sums.
__global__ void __launch_bounds__(256) k2_agg(const float* __restrict__ x,
                                              const float* __restrict__ Wg,
                                              const float* __restrict__ bg) {
    __shared__ float sx[N_NODES * IN_DIM];
    __shared__ int   s_src[256];
    __shared__ float s_w[256];
    __shared__ float red1[256], red2[256];
    int tid = threadIdx.x;
    int n = blockIdx.y;
    int j = blockIdx.x * 256 + tid;

    for (int i = tid; i < N_NODES * IN_DIM; i += 256) sx[i] = x[i];
    float wreg[IN_DIM];
#pragma unroll
    for (int k = 0; k < IN_DIM; k++) wreg[k] = Wg[k * HIDDEN + j];
    __syncthreads();

    float dv = d_dinv[n];
    float hs = 0.f;
#pragma unroll
    for (int k = 0; k < IN_DIM; k++) hs += sx[n * IN_DIM + k] * wreg[k];
    float acc = hs * dv * dv;                        // self loop

    int beg = d_off[n], end = d_off[n + 1];
    for (int base = beg; base < end; base += 256) {
        int m = min(256, end - base);
        if (tid < m) { s_src[tid] = d_csr_src[base + tid]; s_w[tid] = d_csr_w[base + tid]; }
        __syncthreads();
        for (int i = 0; i < m; i++) {
            int s = s_src[i];
            float hv = 0.f;
#pragma unroll
            for (int k = 0; k < IN_DIM; k++) hv += sx[s * IN_DIM + k] * wreg[k];
            acc += hv * s_w[i];
        }
        __syncthreads();
    }
    float v = acc + bg[j];
    v = v > 0.f ? v : 0.f;
    d_h2[n * HIDDEN + j] = v;

    red1[tid] = v;
    red2[tid] = v * v;
    __syncthreads();
    for (int o = 128; o > 0; o >>= 1) {
        if (tid < o) { red1[tid] += red1[tid + o]; red2[tid] += red2[tid + o]; }
        __syncthreads();
    }
    if (tid == 0) {
        atomicAdd(&d_nsum[n], red1[0]);
        atomicAdd(&d_nsq[n], red2[0]);
    }
}

// ---------------------------------------------------------------------------
// K4: layernorm + pool partials, node-split. grid (32, 27).
__global__ void __launch_bounds__(256) k4_pool() {
    __shared__ float s_mu[3], s_rstd[3];
    int tid = threadIdx.x;
    int n0 = blockIdx.y * 3;
    if (tid < 3) {
        float mu = d_nsum[n0 + tid] * (1.f / HIDDEN);
        float var = d_nsq[n0 + tid] * (1.f / HIDDEN) - mu * mu;
        s_mu[tid] = mu;
        s_rstd[tid] = rsqrtf(var + 1e-5f);
    }
    __syncthreads();
    int j = blockIdx.x * 256 + tid;
    float acc = 0.f;
#pragma unroll
    for (int t = 0; t < 3; t++)
        acc += (d_h2[(n0 + t) * HIDDEN + j] - s_mu[t]) * s_rstd[t];
    atomicAdd(&d_gacc[j], acc);
}

// ---------------------------------------------------------------------------
// K6: split-K GEMV t1 += g @ W1. g-chunk finalized once into smem per block;
// inner loop is pure LDG.128 streaming + smem-broadcast FMA.
__global__ void __launch_bounds__(256) k6_gemv1(const float* __restrict__ W1,
                                                const float* __restrict__ lg,
                                                const float* __restrict__ lb) {
    __shared__ float sg[64];
    int tid = threadIdx.x;
    int k0 = blockIdx.y * 64;
    if (tid < 64) {
        int k = k0 + tid;
        sg[tid] = lg[k] * d_gacc[k] + (float)N_NODES * lb[k];
    }
    __syncthreads();

    int ci = blockIdx.x * 256 + tid;                 // float4 column index
    const float4* Wv = reinterpret_cast<const float4*>(W1);
    float4 acc = make_float4(0.f, 0.f, 0.f, 0.f);
#pragma unroll 8
    for (int k = 0; k < 64; k++) {
        float gk = sg[k];
        float4 w = Wv[(size_t)(k0 + k) * (HIDDEN / 4) + ci];
        acc.x += gk * w.x; acc.y += gk * w.y;
        acc.z += gk * w.z; acc.w += gk * w.w;
    }
    int col = ci * 4;
    atomicAdd(&d_t1[col + 0], acc.x);
    atomicAdd(&d_t1[col + 1], acc.y);
    atomicAdd(&d_t1[col + 2], acc.z);
    atomicAdd(&d_t1[col + 3], acc.w);
}

// ---------------------------------------------------------------------------
// K7: logits += relu(t1 + b1) @ W2 (split-K); activation chunk via smem.
__global__ void __launch_bounds__(256) k7_gemv2(const float* __restrict__ W2,
                                                const float* __restrict__ b1) {
    __shared__ float sa[64];
    int tid = threadIdx.x;
    int k0 = blockIdx.y * 64;
    if (tid < 64) {
        float a = d_t1[k0 + tid] + b1[k0 + tid];
        sa[tid] = a > 0.f ? a : 0.f;
    }
    __syncthreads();
    int j = blockIdx.x * 256 + tid;
    if (j >= ACTIONS) return;
    float acc = 0.f;
#pragma unroll 8
    for (int k = 0; k < 64; k++)
        acc += sa[k] * W2[(size_t)(k0 + k) * ACTIONS + j];
    atomicAdd(&d_logits[j], acc);
}

// ---------------------------------------------------------------------------
// K8: log_softmax
__global__ void k8_softmax(const float* __restrict__ b2, float* __restrict__ out) {
    __shared__ float sh[1024];
    int tid = threadIdx.x;
    float l = (tid < ACTIONS) ? d_logits[tid] + b2[tid] : -INFINITY;
    sh[tid] = l;
    __syncthreads();
    for (int o = 512; o > 0; o >>= 1) {
        if (tid < o) sh[tid] = fmaxf(sh[tid], sh[tid + o]);
        __syncthreads();
    }
    float mx = sh[0];
    __syncthreads();
    float ex = (tid < ACTIONS) ? expf(l - mx) : 0.f;
    sh[tid] = ex;
    __syncthreads();
    for (int o = 512; o > 0; o >>= 1) {
        if (tid < o) sh[tid] += sh[tid + o];
        __syncthreads();
    }
    float lse = logf(sh[0]);
    if (tid < ACTIONS) out[tid] = l - mx - lse;
}

extern "C" void kernel_launch(void* const* d_in, const int* in_sizes, int n_in,
                              void* d_out, int out_size) {
    const float* x    = (const float*)d_in[0];
    const int*   edge = (const int*)d_in[1];
    const float* Wg   = (const float*)d_in[2];
    const float* bg   = (const float*)d_in[3];
    const float* lng  = (const float*)d_in[4];
    const float* lnb  = (const float*)d_in[5];
    const float* W1   = (const float*)d_in[6];
    const float* b1   = (const float*)d_in[7];
    const float* W2   = (const float*)d_in[8];
    const float* b2   = (const float*)d_in[9];
    float* out = (float*)d_out;

    k0_prep<<<1, 256>>>(edge);
    k2_agg<<<dim3(HIDDEN / 256, N_NODES), 256>>>(x, Wg, bg);
    k4_pool<<<dim3(HIDDEN / 256, 27), 256>>>();
    k6_gemv1<<<dim3(8, 128), 256>>>(W1, lng, lnb);
    k7_gemv2<<<dim3(3, 128), 256>>>(W2, b1);
    k8_softmax<<<1, 1024>>>(b2, out);
}

// round 6
// speedup vs baseline: 3.2617x; 1.1396x over previous
#include <cuda_runtime.h>
#include <math.h>

#define N_NODES 81
#define N_EDGES 1620
#define IN_DIM 10
#define HIDDEN 8192
#define ACTIONS 729

// Scratch (__device__ globals; no allocation allowed)
__device__ float d_h2[N_NODES * HIDDEN];
__device__ float d_gacc[HIDDEN];
__device__ float d_t1[HIDDEN];
__device__ float d_logits[ACTIONS];
__device__ float d_dinv[N_NODES];
__device__ float d_nsum[N_NODES];
__device__ float d_nsq[N_NODES];
__device__ int   d_csr_src[N_EDGES];
__device__ float d_csr_w[N_EDGES];
__device__ int   d_off[N_NODES + 1];

// ---------------------------------------------------------------------------
// K0: grid of 9 blocks. Block 0 builds CSR; all blocks zero accumulators.
__global__ void k0_prep(const int* __restrict__ edge) {
    int tid = threadIdx.x;
    int gi = blockIdx.x * 256 + tid;
    // parallel zeroing across all 9 blocks
    for (int i = gi; i < HIDDEN; i += 9 * 256) { d_t1[i] = 0.f; d_gacc[i] = 0.f; }
    for (int i = gi; i < ACTIONS; i += 9 * 256) d_logits[i] = 0.f;
    if (gi < N_NODES) { d_nsum[gi] = 0.f; d_nsq[gi] = 0.f; }

    if (blockIdx.x != 0) return;
    __shared__ int cnt[N_NODES];
    __shared__ int off[N_NODES + 1];
    __shared__ float sdinv[N_NODES];
    for (int i = tid; i < N_NODES; i += blockDim.x) cnt[i] = 0;
    __syncthreads();
    for (int e = tid; e < N_EDGES; e += blockDim.x) {
        int d = edge[N_EDGES + e];
        if ((unsigned)d < N_NODES) atomicAdd(&cnt[d], 1);
    }
    __syncthreads();
    for (int i = tid; i < N_NODES; i += blockDim.x) {
        float dv = rsqrtf((float)(cnt[i] + 1));   // +1 self loop
        sdinv[i] = dv;
        d_dinv[i] = dv;
    }
    __syncthreads();
    if (tid == 0) {
        off[0] = 0;
        for (int i = 0; i < N_NODES; i++) off[i + 1] = off[i] + cnt[i];
    }
    __syncthreads();
    for (int i = tid; i <= N_NODES; i += blockDim.x) d_off[i] = off[i];
    for (int i = tid; i < N_NODES; i += blockDim.x) cnt[i] = off[i];  // scatter cursor
    __syncthreads();
    for (int e = tid; e < N_EDGES; e += blockDim.x) {
        int s = edge[e];
        int d = edge[N_EDGES + e];
        if ((unsigned)s < N_NODES && (unsigned)d < N_NODES) {
            int pos = atomicAdd(&cnt[d], 1);
            d_csr_src[pos] = s;
            d_csr_w[pos] = sdinv[s] * sdinv[d];
        }
    }
}

// ---------------------------------------------------------------------------
// K2: fused transform + aggregation + bias + relu + LN partial sums.
__global__ void __launch_bounds__(256) k2_agg(const float* __restrict__ x,
                                              const float* __restrict__ Wg,
                                              const float* __restrict__ bg) {
    __shared__ float sx[N_NODES * IN_DIM];
    __shared__ int   s_src[256];
    __shared__ float s_w[256];
    __shared__ float wsum[8], wsq[8];
    int tid = threadIdx.x;
    int n = blockIdx.y;
    int j = blockIdx.x * 256 + tid;

    for (int i = tid; i < N_NODES * IN_DIM; i += 256) sx[i] = x[i];
    float wreg[IN_DIM];
#pragma unroll
    for (int k = 0; k < IN_DIM; k++) wreg[k] = Wg[k * HIDDEN + j];
    __syncthreads();

    float dv = d_dinv[n];
    float hs = 0.f;
#pragma unroll
    for (int k = 0; k < IN_DIM; k++) hs += sx[n * IN_DIM + k] * wreg[k];
    float acc = hs * dv * dv;                        // self loop

    int beg = d_off[n], end = d_off[n + 1];
    for (int base = beg; base < end; base += 256) {
        int m = min(256, end - base);
        if (tid < m) { s_src[tid] = d_csr_src[base + tid]; s_w[tid] = d_csr_w[base + tid]; }
        __syncthreads();
        for (int i = 0; i < m; i++) {
            int s = s_src[i];
            float hv = 0.f;
#pragma unroll
            for (int k = 0; k < IN_DIM; k++) hv += sx[s * IN_DIM + k] * wreg[k];
            acc += hv * s_w[i];
        }
        __syncthreads();
    }
    float v = acc + bg[j];
    v = v > 0.f ? v : 0.f;
    d_h2[n * HIDDEN + j] = v;

    // warp-shuffle LN partials, one atomic pair per block
    float v1 = v, v2 = v * v;
#pragma unroll
    for (int o = 16; o > 0; o >>= 1) {
        v1 += __shfl_down_sync(0xffffffffu, v1, o);
        v2 += __shfl_down_sync(0xffffffffu, v2, o);
    }
    int warp = tid >> 5, lane = tid & 31;
    if (lane == 0) { wsum[warp] = v1; wsq[warp] = v2; }
    __syncthreads();
    if (tid == 0) {
        float s1 = 0.f, s2 = 0.f;
#pragma unroll
        for (int w = 0; w < 8; w++) { s1 += wsum[w]; s2 += wsq[w]; }
        atomicAdd(&d_nsum[n], s1);
        atomicAdd(&d_nsq[n], s2);
    }
}

// ---------------------------------------------------------------------------
// K4: layernorm + pool partials, node-split. grid (32, 27).
__global__ void __launch_bounds__(256) k4_pool() {
    __shared__ float s_mu[3], s_rstd[3];
    int tid = threadIdx.x;
    int n0 = blockIdx.y * 3;
    if (tid < 3) {
        float mu = d_nsum[n0 + tid] * (1.f / HIDDEN);
        float var = d_nsq[n0 + tid] * (1.f / HIDDEN) - mu * mu;
        s_mu[tid] = mu;
        s_rstd[tid] = rsqrtf(var + 1e-5f);
    }
    __syncthreads();
    int j = blockIdx.x * 256 + tid;
    float acc = 0.f;
#pragma unroll
    for (int t = 0; t < 3; t++)
        acc += (d_h2[(n0 + t) * HIDDEN + j] - s_mu[t]) * s_rstd[t];
    atomicAdd(&d_gacc[j], acc);
}

// ---------------------------------------------------------------------------
// K6: split-K GEMV t1 += g @ W1. Explicit 8-deep load batches (true MLP=8),
// streaming loads, 64-register budget.
__global__ void __launch_bounds__(256, 4) k6_gemv1(const float* __restrict__ W1,
                                                   const float* __restrict__ lg,
                                                   const float* __restrict__ lb) {
    __shared__ float sg[64];
    int tid = threadIdx.x;
    int k0 = blockIdx.y * 64;
    if (tid < 64) {
        int k = k0 + tid;
        sg[tid] = lg[k] * d_gacc[k] + (float)N_NODES * lb[k];
    }
    __syncthreads();

    int ci = blockIdx.x * 256 + tid;                 // float4 column index
    const float4* base = reinterpret_cast<const float4*>(W1) + (size_t)k0 * (HIDDEN / 4) + ci;
    float4 acc = make_float4(0.f, 0.f, 0.f, 0.f);
#pragma unroll
    for (int k = 0; k < 64; k += 8) {
        float4 w[8];
#pragma unroll
        for (int u = 0; u < 8; u++)
            w[u] = __ldcs(base + (size_t)(k + u) * (HIDDEN / 4));
#pragma unroll
        for (int u = 0; u < 8; u++) {
            float gk = sg[k + u];
            acc.x += gk * w[u].x; acc.y += gk * w[u].y;
            acc.z += gk * w[u].z; acc.w += gk * w[u].w;
        }
    }
    int col = ci * 4;
    atomicAdd(&d_t1[col + 0], acc.x);
    atomicAdd(&d_t1[col + 1], acc.y);
    atomicAdd(&d_t1[col + 2], acc.z);
    atomicAdd(&d_t1[col + 3], acc.w);
}

// ---------------------------------------------------------------------------
// K7: logits += relu(t1 + b1) @ W2 (split-K); explicit load batches.
__global__ void __launch_bounds__(256, 4) k7_gemv2(const float* __restrict__ W2,
                                                   const float* __restrict__ b1) {
    __shared__ float sa[64];
    int tid = threadIdx.x;
    int k0 = blockIdx.y * 64;
    if (tid < 64) {
        float a = d_t1[k0 + tid] + b1[k0 + tid];
        sa[tid] = a > 0.f ? a : 0.f;
    }
    __syncthreads();
    int j = blockIdx.x * 256 + tid;
    if (j >= ACTIONS) return;
    const float* base = W2 + (size_t)k0 * ACTIONS + j;
    float acc = 0.f;
#pragma unroll
    for (int k = 0; k < 64; k += 8) {
        float w[8];
#pragma unroll
        for (int u = 0; u < 8; u++)
            w[u] = __ldcs(base + (size_t)(k + u) * ACTIONS);
#pragma unroll
        for (int u = 0; u < 8; u++)
            acc += sa[k + u] * w[u];
    }
    atomicAdd(&d_logits[j], acc);
}

// ---------------------------------------------------------------------------
// K8: log_softmax
__global__ void k8_softmax(const float* __restrict__ b2, float* __restrict__ out) {
    __shared__ float sh[1024];
    int tid = threadIdx.x;
    float l = (tid < ACTIONS) ? d_logits[tid] + b2[tid] : -INFINITY;
    sh[tid] = l;
    __syncthreads();
    for (int o = 512; o > 0; o >>= 1) {
        if (tid < o) sh[tid] = fmaxf(sh[tid], sh[tid + o]);
        __syncthreads();
    }
    float mx = sh[0];
    __syncthreads();
    float ex = (tid < ACTIONS) ? expf(l - mx) : 0.f;
    sh[tid] = ex;
    __syncthreads();
    for (int o = 512; o > 0; o >>= 1) {
        if (tid < o) sh[tid] += sh[tid + o];
        __syncthreads();
    }
    float lse = logf(sh[0]);
    if (tid < ACTIONS) out[tid] = l - mx - lse;
}

extern "C" void kernel_launch(void* const* d_in, const int* in_sizes, int n_in,
                              void* d_out, int out_size) {
    const float* x    = (const float*)d_in[0];
    const int*   edge = (const int*)d_in[1];
    const float* Wg   = (const float*)d_in[2];
    const float* bg   = (const float*)d_in[3];
    const float* lng  = (const float*)d_in[4];
    const float* lnb  = (const float*)d_in[5];
    const float* W1   = (const float*)d_in[6];
    const float* b1   = (const float*)d_in[7];
    const float* W2   = (const float*)d_in[8];
    const float* b2   = (const float*)d_in[9];
    float* out = (float*)d_out;

    k0_prep<<<9, 256>>>(edge);
    k2_agg<<<dim3(HIDDEN / 256, N_NODES), 256>>>(x, Wg, bg);
    k4_pool<<<dim3(HIDDEN / 256, 27), 256>>>();
    k6_gemv1<<<dim3(8, 128), 256>>>(W1, lng, lnb);
    k7_gemv2<<<dim3(3, 128), 256>>>(W2, b1);
    k8_softmax<<<1, 1024>>>(b2, out);
}